// round 1
// baseline (speedup 1.0000x reference)
#include <cuda_runtime.h>
#include <math_constants.h>

// ---------------------------------------------------------------------------
// Exact Euclidean k-NN:  Q=1024 queries x N=250000 base x D=128, k=10.
// d2 = |q|^2 - 2 q.b + |b|^2  (matches reference formula, fp32 throughout)
//
// Phase 0: b_sq[n] = |base_n|^2               (warp-per-row reduction)
// Phase 1: fused GEMV + per-chunk top-10      (thread-per-query, 148 blocks)
// Phase 2: merge 37 chunk-candidate lists per query, sort, write output
// ---------------------------------------------------------------------------

#define D128     128
#define D4       32          // D/4 float4s
#define NCHUNK   37          // 37 chunks x 4 query-blocks = 148 blocks = 1 wave
#define QB       256         // queries per block (1 per thread)
#define TB       64          // base rows per smem tile
#define KSEL     10          // top-k kept per thread

#define MAXN     262144
#define MAXQ     1024

// scratch (device globals: allocation-free rule)
__device__ float g_bsq[MAXN];
__device__ float g_cand_d[MAXQ * NCHUNK * KSEL];
__device__ int   g_cand_i[MAXQ * NCHUNK * KSEL];

// ---------------------------------------------------------------------------
// Phase 0: squared norms of base rows. One warp per row, float4 loads.
// ---------------------------------------------------------------------------
__global__ void bsq_kernel(const float* __restrict__ base, int N) {
    int row  = blockIdx.x * 8 + (threadIdx.x >> 5);
    if (row >= N) return;
    int lane = threadIdx.x & 31;
    float4 v = reinterpret_cast<const float4*>(base)[row * D4 + lane];
    float s = v.x * v.x + v.y * v.y + v.z * v.z + v.w * v.w;
    #pragma unroll
    for (int o = 16; o > 0; o >>= 1) s += __shfl_xor_sync(0xFFFFFFFFu, s, o);
    if (lane == 0) g_bsq[row] = s;
}

// ---------------------------------------------------------------------------
// Phase 1: each thread owns one query (full row in registers) and streams a
// base chunk through shared memory, maintaining a private top-10 of d2.
// ---------------------------------------------------------------------------
__global__ void __launch_bounds__(QB, 1)
knn_partial_kernel(const float* __restrict__ base,
                   const float* __restrict__ query,
                   int N, int Q) {
    __shared__ float4 s_tile[TB * D4];   // 64 rows x 128 floats = 32 KB
    __shared__ float  s_bsq[TB];

    const int chunk = blockIdx.x;
    const int q     = blockIdx.y * QB + threadIdx.x;
    const int tid   = threadIdx.x;

    const int chunk_len = (N + NCHUNK - 1) / NCHUNK;
    const int cs = chunk * chunk_len;
    const int ce = min(cs + chunk_len, N);

    // query row -> registers (32 x float4)
    float4 qv[D4];
    if (q < Q) {
        const float4* qrow = reinterpret_cast<const float4*>(query) + q * D4;
        #pragma unroll
        for (int i = 0; i < D4; ++i) qv[i] = qrow[i];
    } else {
        #pragma unroll
        for (int i = 0; i < D4; ++i) qv[i] = make_float4(0.f, 0.f, 0.f, 0.f);
    }
    float qsq = 0.f;
    #pragma unroll
    for (int i = 0; i < D4; ++i) {
        qsq += qv[i].x * qv[i].x + qv[i].y * qv[i].y
             + qv[i].z * qv[i].z + qv[i].w * qv[i].w;
    }

    // thread-local top-10 (unsorted, max-tracked)
    float td[KSEL];
    int   ti[KSEL];
    #pragma unroll
    for (int j = 0; j < KSEL; ++j) { td[j] = CUDART_INF_F; ti[j] = -1; }
    float kmax = CUDART_INF_F;

    const float4* base4 = reinterpret_cast<const float4*>(base);
    const int ntiles = (ce - cs + TB - 1) >> 6;

    for (int t = 0; t < ntiles; ++t) {
        const int n0 = cs + t * TB;

        // cooperative tile load: 64 x 32 float4, fully coalesced
        #pragma unroll
        for (int k = 0; k < (TB * D4) / QB; ++k) {      // 8 per thread
            int i = tid + k * QB;
            int n = n0 + (i >> 5);                      // i / 32 = row
            s_tile[i] = (n < N) ? base4[n * D4 + (i & 31)]
                                : make_float4(0.f, 0.f, 0.f, 0.f);
        }
        if (tid < TB) {
            int n = n0 + tid;
            s_bsq[tid] = (n < ce) ? g_bsq[n] : CUDART_INF_F;
        }
        __syncthreads();

        // 4 base rows at a time: 128 broadcast LDS.128 + 512 FFMA per group
        for (int b = 0; b < TB; b += 4) {
            float acc0 = 0.f, acc1 = 0.f, acc2 = 0.f, acc3 = 0.f;
            #pragma unroll
            for (int d4 = 0; d4 < D4; ++d4) {
                float4 qd = qv[d4];
                float4 b0 = s_tile[(b + 0) * D4 + d4];
                float4 b1 = s_tile[(b + 1) * D4 + d4];
                float4 b2 = s_tile[(b + 2) * D4 + d4];
                float4 b3 = s_tile[(b + 3) * D4 + d4];
                acc0 += qd.x * b0.x + qd.y * b0.y + qd.z * b0.z + qd.w * b0.w;
                acc1 += qd.x * b1.x + qd.y * b1.y + qd.z * b1.z + qd.w * b1.w;
                acc2 += qd.x * b2.x + qd.y * b2.y + qd.z * b2.z + qd.w * b2.w;
                acc3 += qd.x * b3.x + qd.y * b3.y + qd.z * b3.z + qd.w * b3.w;
            }
            float acc[4] = {acc0, acc1, acc2, acc3};
            #pragma unroll
            for (int j = 0; j < 4; ++j) {
                float d2 = qsq - 2.0f * acc[j] + s_bsq[b + j];
                if (d2 < kmax) {                         // strict <: keep earlier index on tie
                    bool done = false;
                    #pragma unroll
                    for (int s = 0; s < KSEL; ++s) {
                        if (!done && td[s] == kmax) {
                            td[s] = d2; ti[s] = n0 + b + j; done = true;
                        }
                    }
                    kmax = td[0];
                    #pragma unroll
                    for (int s = 1; s < KSEL; ++s) kmax = fmaxf(kmax, td[s]);
                }
            }
        }
        __syncthreads();
    }

    if (q < Q) {
        int o = (q * NCHUNK + chunk) * KSEL;
        #pragma unroll
        for (int j = 0; j < KSEL; ++j) {
            g_cand_d[o + j] = td[j];
            g_cand_i[o + j] = ti[j];
        }
    }
}

// ---------------------------------------------------------------------------
// Phase 2: merge NCHUNK*10 candidates per query, sort ascending (index
// tie-break), write [indices-as-float | distances].
// ---------------------------------------------------------------------------
__global__ void knn_merge_kernel(float* __restrict__ out, int Q, int K) {
    int q = blockIdx.x * blockDim.x + threadIdx.x;
    if (q >= Q) return;

    float td[KSEL];
    int   ti[KSEL];
    #pragma unroll
    for (int j = 0; j < KSEL; ++j) { td[j] = CUDART_INF_F; ti[j] = -1; }
    float kmax = CUDART_INF_F;

    const float* cd = g_cand_d + q * NCHUNK * KSEL;
    const int*   ci = g_cand_i + q * NCHUNK * KSEL;

    for (int j = 0; j < NCHUNK * KSEL; ++j) {
        float v = cd[j];
        if (v < kmax) {
            int idx = ci[j];
            bool done = false;
            #pragma unroll
            for (int s = 0; s < KSEL; ++s) {
                if (!done && td[s] == kmax) { td[s] = v; ti[s] = idx; done = true; }
            }
            kmax = td[0];
            #pragma unroll
            for (int s = 1; s < KSEL; ++s) kmax = fmaxf(kmax, td[s]);
        }
    }

    // insertion sort ascending by (d2, idx)
    #pragma unroll
    for (int i = 1; i < KSEL; ++i) {
        float dv = td[i]; int iv = ti[i];
        int j = i - 1;
        while (j >= 0 && (td[j] > dv || (td[j] == dv && ti[j] > iv))) {
            td[j + 1] = td[j]; ti[j + 1] = ti[j]; --j;
        }
        td[j + 1] = dv; ti[j + 1] = iv;
    }

    int kk = (K < KSEL) ? K : KSEL;
    for (int r = 0; r < kk; ++r) {
        out[q * K + r]         = (float)ti[r];                  // indices block
        out[Q * K + q * K + r] = sqrtf(fmaxf(td[r], 0.0f));     // distances block
    }
}

// ---------------------------------------------------------------------------
extern "C" void kernel_launch(void* const* d_in, const int* in_sizes, int n_in,
                              void* d_out, int out_size) {
    const float* base  = (const float*)d_in[0];
    const float* query = (const float*)d_in[1];
    // d_in[2] = k_query on device; k derived from out_size instead (host side)

    int N = in_sizes[0] / D128;
    int Q = in_sizes[1] / D128;
    int K = (Q > 0) ? out_size / (2 * Q) : KSEL;
    if (K <= 0 || K > KSEL) K = KSEL;

    bsq_kernel<<<(N + 7) / 8, 256>>>(base, N);

    dim3 grid(NCHUNK, (Q + QB - 1) / QB);
    knn_partial_kernel<<<grid, QB>>>(base, query, N, Q);

    knn_merge_kernel<<<(Q + 127) / 128, 128>>>((float*)d_out, Q, K);
}